// round 1
// baseline (speedup 1.0000x reference)
#include <cuda_runtime.h>
#include <math.h>

#define NB   4
#define HW   4096
#define DH   128
#define NTOK 4096

// Scratch (device globals: allocation-free per harness rules). 8 MB each.
__device__ float g_Q [NB * NTOK * DH];
__device__ float g_Kt[NB * NTOK * DH];   // K stored transposed: [B][D][N]
__device__ float g_V [NB * NTOK * DH];
__device__ float g_O [NB * NTOK * DH];

// ---------------------------------------------------------------------------
// 1x1 conv (GEMM): out[b][c][s] = bias[c] + sum_i w[c][i] * x[b][i][s] (+res)
// Block computes [32 out-channels][256 spatial] with 16-deep k chunks in smem.
// TRANS=true writes output in [D][N] token-transposed layout (for K).
// ---------------------------------------------------------------------------
template<int CIN, bool TRANS, bool RES>
__global__ __launch_bounds__(256) void proj_kernel(
    const float* __restrict__ x, const float* __restrict__ w,
    const float* __restrict__ bias, const float* __restrict__ res,
    float* __restrict__ out)
{
    __shared__ float xs[16][256];
    __shared__ float ws[32][16];

    const int b   = blockIdx.z;
    const int c0  = blockIdx.y * 32;
    const int s0  = blockIdx.x * 256;
    const int tid = threadIdx.x;
    const int tx  = tid & 63;    // spatial group: s = s0 + 4*tx
    const int ty  = tid >> 6;    // channel group: c = c0 + 8*ty + cc

    float acc[8][4];
#pragma unroll
    for (int i = 0; i < 8; i++)
#pragma unroll
        for (int j = 0; j < 4; j++) acc[i][j] = 0.f;

    for (int k0 = 0; k0 < CIN; k0 += 16) {
        __syncthreads();
#pragma unroll
        for (int t = 0; t < 4; t++) {
            int f  = tid + 256 * t;          // 1024 float4s = 16x256 floats
            int r  = f >> 6;
            int c4 = (f & 63) << 2;
            float4 v = *(const float4*)(x + ((size_t)b * CIN + k0 + r) * HW + s0 + c4);
            *(float4*)&xs[r][c4] = v;
        }
#pragma unroll
        for (int t = 0; t < 2; t++) {
            int f  = tid + 256 * t;          // 512 = 32x16 weights
            int cr = f >> 4, ck = f & 15;
            ws[cr][ck] = w[(size_t)(c0 + cr) * CIN + k0 + ck];
        }
        __syncthreads();
#pragma unroll
        for (int k = 0; k < 16; k++) {
            float4 xv = *(float4*)&xs[k][tx << 2];
#pragma unroll
            for (int cc = 0; cc < 8; cc++) {
                float wv = ws[ty * 8 + cc][k];
                acc[cc][0] = fmaf(wv, xv.x, acc[cc][0]);
                acc[cc][1] = fmaf(wv, xv.y, acc[cc][1]);
                acc[cc][2] = fmaf(wv, xv.z, acc[cc][2]);
                acc[cc][3] = fmaf(wv, xv.w, acc[cc][3]);
            }
        }
    }

#pragma unroll
    for (int cc = 0; cc < 8; cc++) {
        const int c  = c0 + ty * 8 + cc;
        const float bv = bias[c];
        const int s  = s0 + (tx << 2);
        if (!TRANS) {
            float4 o;
            o.x = acc[cc][0] + bv; o.y = acc[cc][1] + bv;
            o.z = acc[cc][2] + bv; o.w = acc[cc][3] + bv;
            if (RES) {
                float4 rv = *(const float4*)(res + ((size_t)b * DH + c) * HW + s);
                o.x += rv.x; o.y += rv.y; o.z += rv.z; o.w += rv.w;
            }
            *(float4*)(out + ((size_t)b * DH + c) * HW + s) = o;
        } else {
            // token-transposed store: flat = c*HW + s; token n = flat>>7, d = flat&127
#pragma unroll
            for (int u = 0; u < 4; u++) {
                int ss = s + u;
                int d  = ss & 127;
                int n  = c * 32 + (ss >> 7);
                out[(size_t)b * NTOK * DH + (size_t)d * NTOK + n] = acc[cc][u] + bv;
            }
        }
    }
}

// ---------------------------------------------------------------------------
// fp32 flash attention: BM=64 queries/block, BN=64 key tile, D=128.
// 256 threads: S stage 16x16 grid of 4x4 micro-tiles; PV stage 4x8 per thread.
// Online softmax with per-row (m, l) kept redundantly in registers (intra-warp
// shfl reductions across the 16 tx lanes that share each row group).
// ---------------------------------------------------------------------------
__global__ __launch_bounds__(256) void flash_kernel(
    const float* __restrict__ Q, const float* __restrict__ Ktg,
    const float* __restrict__ V, float* __restrict__ O)
{
    extern __shared__ float sm[];
    float* Qs = sm;                       // [64][132]
    float* Kt = sm + 64 * 132;            // [128][68]  (d-major, j minor)
    float* Vs = Kt + 128 * 68;            // [64][128]
    float* Ps = Vs + 64 * 128;            // [64][68]

    const int b   = blockIdx.y;
    const int m0  = blockIdx.x * 64;
    const int tid = threadIdx.x;
    const int tx  = tid & 15;
    const int ty  = tid >> 4;
    const int i0  = ty << 2;              // 4 query rows per thread
    const int j0  = tx << 2;              // 4 key cols (S) / d-offset (PV)

    const float* Qb = Q   + ((size_t)b * NTOK + m0) * DH;
    const float* Kb = Ktg + (size_t)b * NTOK * DH;     // [128][4096]
    const float* Vb = V   + (size_t)b * NTOK * DH;
    const float qscale = 0.08838834764831845f;         // 1/sqrt(128)

    // Load Q tile, pre-scaled
#pragma unroll
    for (int t = 0; t < 8; t++) {
        int f  = tid + 256 * t;           // 2048 float4 = 64x128
        int r  = f >> 5;
        int c4 = (f & 31) << 2;
        float4 v = *(const float4*)(Qb + r * DH + c4);
        v.x *= qscale; v.y *= qscale; v.z *= qscale; v.w *= qscale;
        *(float4*)&Qs[r * 132 + c4] = v;
    }

    float acc[4][8];
#pragma unroll
    for (int r = 0; r < 4; r++)
#pragma unroll
        for (int d = 0; d < 8; d++) acc[r][d] = 0.f;
    float mrow[4] = {-1e30f, -1e30f, -1e30f, -1e30f};
    float lrow[4] = {0.f, 0.f, 0.f, 0.f};

    for (int n0 = 0; n0 < NTOK; n0 += 64) {
        __syncthreads();   // previous iter's readers of Kt/Vs/Ps are done
#pragma unroll
        for (int t = 0; t < 8; t++) {
            int f  = tid + 256 * t;
            // K tile: [128 d][64 j] from transposed gmem (coalesced rows)
            int r  = f >> 4;
            int c4 = (f & 15) << 2;
            float4 kv = *(const float4*)(Kb + (size_t)r * NTOK + n0 + c4);
            *(float4*)&Kt[r * 68 + c4] = kv;
            // V tile: [64 j][128 d] natural
            int rv = f >> 5;
            int cv = (f & 31) << 2;
            float4 vv = *(const float4*)(Vb + (size_t)(n0 + rv) * DH + cv);
            *(float4*)&Vs[rv * 128 + cv] = vv;
        }
        __syncthreads();

        // ---- S = (Q/sqrt(d)) @ K^T  (4x4 per thread) ----
        float s[4][4];
#pragma unroll
        for (int r = 0; r < 4; r++)
#pragma unroll
            for (int c = 0; c < 4; c++) s[r][c] = 0.f;

#pragma unroll 4
        for (int k = 0; k < 128; k += 4) {
            float4 kb[4];
            kb[0] = *(float4*)&Kt[(k + 0) * 68 + j0];
            kb[1] = *(float4*)&Kt[(k + 1) * 68 + j0];
            kb[2] = *(float4*)&Kt[(k + 2) * 68 + j0];
            kb[3] = *(float4*)&Kt[(k + 3) * 68 + j0];
#pragma unroll
            for (int r = 0; r < 4; r++) {
                float4 qa = *(float4*)&Qs[(i0 + r) * 132 + k];
                float qv[4] = {qa.x, qa.y, qa.z, qa.w};
#pragma unroll
                for (int kk = 0; kk < 4; kk++) {
                    s[r][0] = fmaf(qv[kk], kb[kk].x, s[r][0]);
                    s[r][1] = fmaf(qv[kk], kb[kk].y, s[r][1]);
                    s[r][2] = fmaf(qv[kk], kb[kk].z, s[r][2]);
                    s[r][3] = fmaf(qv[kk], kb[kk].w, s[r][3]);
                }
            }
        }

        // ---- online softmax update ----
#pragma unroll
        for (int r = 0; r < 4; r++) {
            float rm = fmaxf(fmaxf(s[r][0], s[r][1]), fmaxf(s[r][2], s[r][3]));
            rm = fmaxf(rm, __shfl_xor_sync(0xffffffffu, rm, 1));
            rm = fmaxf(rm, __shfl_xor_sync(0xffffffffu, rm, 2));
            rm = fmaxf(rm, __shfl_xor_sync(0xffffffffu, rm, 4));
            rm = fmaxf(rm, __shfl_xor_sync(0xffffffffu, rm, 8));
            float mn  = fmaxf(mrow[r], rm);
            float scl = __expf(mrow[r] - mn);
            mrow[r] = mn;
            float rs = 0.f;
#pragma unroll
            for (int c = 0; c < 4; c++) {
                float p = __expf(s[r][c] - mn);
                s[r][c] = p;
                rs += p;
            }
            rs += __shfl_xor_sync(0xffffffffu, rs, 1);
            rs += __shfl_xor_sync(0xffffffffu, rs, 2);
            rs += __shfl_xor_sync(0xffffffffu, rs, 4);
            rs += __shfl_xor_sync(0xffffffffu, rs, 8);
            lrow[r] = lrow[r] * scl + rs;
#pragma unroll
            for (int d = 0; d < 8; d++) acc[r][d] *= scl;
            *(float4*)&Ps[(i0 + r) * 68 + j0] = make_float4(s[r][0], s[r][1], s[r][2], s[r][3]);
        }
        __syncthreads();

        // ---- acc += P @ V  (rows i0..i0+3, cols {j0..j0+3, 64+j0..64+j0+3}) ----
#pragma unroll 2
        for (int j = 0; j < 64; j += 4) {
            float4 pa[4];
#pragma unroll
            for (int r = 0; r < 4; r++) pa[r] = *(float4*)&Ps[(i0 + r) * 68 + j];
#pragma unroll
            for (int jj = 0; jj < 4; jj++) {
                float4 v0 = *(float4*)&Vs[(j + jj) * 128 + j0];
                float4 v1 = *(float4*)&Vs[(j + jj) * 128 + 64 + j0];
#pragma unroll
                for (int r = 0; r < 4; r++) {
                    float p = (jj == 0) ? pa[r].x : (jj == 1) ? pa[r].y
                            : (jj == 2) ? pa[r].z : pa[r].w;
                    acc[r][0] = fmaf(p, v0.x, acc[r][0]);
                    acc[r][1] = fmaf(p, v0.y, acc[r][1]);
                    acc[r][2] = fmaf(p, v0.z, acc[r][2]);
                    acc[r][3] = fmaf(p, v0.w, acc[r][3]);
                    acc[r][4] = fmaf(p, v1.x, acc[r][4]);
                    acc[r][5] = fmaf(p, v1.y, acc[r][5]);
                    acc[r][6] = fmaf(p, v1.z, acc[r][6]);
                    acc[r][7] = fmaf(p, v1.w, acc[r][7]);
                }
            }
        }
    }

    // ---- epilogue: O = acc / l ----
    float* Ob = O + ((size_t)b * NTOK + m0) * DH;
#pragma unroll
    for (int r = 0; r < 4; r++) {
        float inv = 1.0f / lrow[r];
        float4 o0 = make_float4(acc[r][0] * inv, acc[r][1] * inv,
                                acc[r][2] * inv, acc[r][3] * inv);
        float4 o1 = make_float4(acc[r][4] * inv, acc[r][5] * inv,
                                acc[r][6] * inv, acc[r][7] * inv);
        *(float4*)(Ob + (i0 + r) * DH + j0)      = o0;
        *(float4*)(Ob + (i0 + r) * DH + 64 + j0) = o1;
    }
}

static const int FLASH_SMEM = (64 * 132 + 128 * 68 + 64 * 128 + 64 * 68) * 4; // 118784 B

extern "C" void kernel_launch(void* const* d_in, const int* in_sizes, int n_in,
                              void* d_out, int out_size)
{
    const float* x_upper = (const float*)d_in[0];
    const float* x_lower = (const float*)d_in[1];
    const float* wq = (const float*)d_in[2];
    const float* bq = (const float*)d_in[3];
    const float* wk = (const float*)d_in[4];
    const float* bk = (const float*)d_in[5];
    const float* wv = (const float*)d_in[6];
    const float* bv = (const float*)d_in[7];
    const float* wo = (const float*)d_in[8];
    const float* bo = (const float*)d_in[9];
    float* out = (float*)d_out;

    float *Qp, *Ktp, *Vp, *Op;
    cudaGetSymbolAddress((void**)&Qp,  g_Q);
    cudaGetSymbolAddress((void**)&Ktp, g_Kt);
    cudaGetSymbolAddress((void**)&Vp,  g_V);
    cudaGetSymbolAddress((void**)&Op,  g_O);

    cudaFuncSetAttribute(flash_kernel,
                         cudaFuncAttributeMaxDynamicSharedMemorySize, FLASH_SMEM);

    dim3 pb(256);
    dim3 pg(HW / 256, DH / 32, NB);     // (16, 4, 4)

    proj_kernel<64,  false, false><<<pg, pb>>>(x_upper, wq, bq, nullptr, Qp);
    proj_kernel<128, true,  false><<<pg, pb>>>(x_lower, wk, bk, nullptr, Ktp);
    proj_kernel<128, false, false><<<pg, pb>>>(x_lower, wv, bv, nullptr, Vp);

    flash_kernel<<<dim3(NTOK / 64, NB), 256, FLASH_SMEM>>>(Qp, Ktp, Vp, Op);

    proj_kernel<128, false, true><<<pg, pb>>>(Op, wo, bo, x_lower, out);
}

// round 2
// speedup vs baseline: 3.5983x; 3.5983x over previous
#include <cuda_runtime.h>
#include <math.h>
#include <stdint.h>

#define NB   4
#define HW   4096
#define DH   128
#define NTOK 4096

// Scratch buffers (device globals; allocation-free).
// Q: A-fragment-major  [b][mt(256)][ks(16)][lane(32)][4]   (tf32 bits)
// K: B-fragment-major  [b][nt(512)][ks(16)][lane(32)][2]   (tf32 bits)
// V: B-fragment-major  [b][js(512)][dt(16)][lane(32)][2]   (tf32 bits)
// O: plain             [b][n][d]  (== NCHW flat, consumed by final conv)
__device__ float g_Q[NB * NTOK * DH];
__device__ float g_K[NB * NTOK * DH];
__device__ float g_V[NB * NTOK * DH];
__device__ float g_O[NB * NTOK * DH];

__device__ __forceinline__ uint32_t f2tf32(float x) {
    uint32_t u; asm("cvt.rna.tf32.f32 %0, %1;" : "=r"(u) : "f"(x)); return u;
}

__device__ __forceinline__ void mma_tf32(float* d,
    uint32_t a0, uint32_t a1, uint32_t a2, uint32_t a3,
    uint32_t b0, uint32_t b1)
{
    asm volatile(
        "mma.sync.aligned.m16n8k8.row.col.f32.tf32.tf32.f32 "
        "{%0,%1,%2,%3},{%4,%5,%6,%7},{%8,%9},{%0,%1,%2,%3};"
        : "+f"(d[0]), "+f"(d[1]), "+f"(d[2]), "+f"(d[3])
        : "r"(a0), "r"(a1), "r"(a2), "r"(a3), "r"(b0), "r"(b1));
}

__device__ __forceinline__ void cp_async16(void* smem_dst, const void* gmem_src) {
    uint32_t s = (uint32_t)__cvta_generic_to_shared(smem_dst);
    asm volatile("cp.async.cg.shared.global [%0], [%1], 16;\n" :: "r"(s), "l"(gmem_src));
}
#define CP_COMMIT() asm volatile("cp.async.commit_group;\n" ::: "memory")
template<int N> __device__ __forceinline__ void cp_wait() {
    asm volatile("cp.async.wait_group %0;\n" :: "n"(N) : "memory");
}

// ---------------------------------------------------------------------------
// 1x1 conv (GEMM). MODE: 0 = plain fp32 NCHW (+optional residual),
//                        1 = Q A-frag tf32 (pre-scaled by 1/sqrt(128)),
//                        2 = K B-frag tf32,  3 = V B-frag tf32.
// ---------------------------------------------------------------------------
template<int CIN, int MODE, bool RES>
__global__ __launch_bounds__(256) void proj_kernel(
    const float* __restrict__ x, const float* __restrict__ w,
    const float* __restrict__ bias, const float* __restrict__ res,
    float* __restrict__ out)
{
    __shared__ float xs[16][256];
    __shared__ float ws[32][16];

    const int b   = blockIdx.z;
    const int c0  = blockIdx.y * 32;
    const int s0  = blockIdx.x * 256;
    const int tid = threadIdx.x;
    const int tx  = tid & 63;
    const int ty  = tid >> 6;

    float acc[8][4];
#pragma unroll
    for (int i = 0; i < 8; i++)
#pragma unroll
        for (int j = 0; j < 4; j++) acc[i][j] = 0.f;

    for (int k0 = 0; k0 < CIN; k0 += 16) {
        __syncthreads();
#pragma unroll
        for (int t = 0; t < 4; t++) {
            int f  = tid + 256 * t;
            int r  = f >> 6;
            int c4 = (f & 63) << 2;
            float4 v = *(const float4*)(x + ((size_t)b * CIN + k0 + r) * HW + s0 + c4);
            *(float4*)&xs[r][c4] = v;
        }
#pragma unroll
        for (int t = 0; t < 2; t++) {
            int f  = tid + 256 * t;
            int cr = f >> 4, ck = f & 15;
            ws[cr][ck] = w[(size_t)(c0 + cr) * CIN + k0 + ck];
        }
        __syncthreads();
#pragma unroll
        for (int k = 0; k < 16; k++) {
            float4 xv = *(float4*)&xs[k][tx << 2];
#pragma unroll
            for (int cc = 0; cc < 8; cc++) {
                float wv = ws[ty * 8 + cc][k];
                acc[cc][0] = fmaf(wv, xv.x, acc[cc][0]);
                acc[cc][1] = fmaf(wv, xv.y, acc[cc][1]);
                acc[cc][2] = fmaf(wv, xv.z, acc[cc][2]);
                acc[cc][3] = fmaf(wv, xv.w, acc[cc][3]);
            }
        }
    }

    const float qscale = 0.08838834764831845f;  // 1/sqrt(128)
    uint32_t* outu = (uint32_t*)out;

#pragma unroll
    for (int cc = 0; cc < 8; cc++) {
        const int c  = c0 + ty * 8 + cc;
        const float bv = bias[c];
        const int s  = s0 + (tx << 2);
        if (MODE == 0) {
            float4 o;
            o.x = acc[cc][0] + bv; o.y = acc[cc][1] + bv;
            o.z = acc[cc][2] + bv; o.w = acc[cc][3] + bv;
            if (RES) {
                float4 rv = *(const float4*)(res + ((size_t)b * DH + c) * HW + s);
                o.x += rv.x; o.y += rv.y; o.z += rv.z; o.w += rv.w;
            }
            *(float4*)(out + ((size_t)b * DH + c) * HW + s) = o;
        } else {
#pragma unroll
            for (int u = 0; u < 4; u++) {
                int ss = s + u;
                int d  = ss & 127;          // token dim
                int n  = c * 32 + (ss >> 7);// token index
                float v = acc[cc][u] + bv;
                size_t idx;
                if (MODE == 1) {            // Q: A-frag  (m16k8)
                    v *= qscale;
                    int mt = n >> 4, rr = n & 15;
                    int gg = rr & 7, hi = rr >> 3;
                    int ks = d >> 3, kk = d & 7;
                    int cqe = kk & 3, ch = kk >> 2;
                    int lane = gg * 4 + cqe;
                    int j = hi + 2 * ch;
                    idx = ((((size_t)b * 256 + mt) * 16 + ks) << 7) + lane * 4 + j;
                } else if (MODE == 2) {     // K: B-frag (k8n8), k = d, n = token
                    int nt = n >> 3, gp = n & 7;
                    int ks = d >> 3, kk = d & 7;
                    int cp = kk & 3, j = kk >> 2;
                    int lane = gp * 4 + cp;
                    idx = ((((size_t)b * 512 + nt) * 16 + ks) << 6) + lane * 2 + j;
                } else {                    // V: B-frag (k8n8), k = token, n = d
                    int js = n >> 3, kk = n & 7;
                    int cp = kk & 3, j = kk >> 2;
                    int dt = d >> 3, gp = d & 7;
                    int lane = gp * 4 + cp;
                    idx = ((((size_t)b * 512 + js) * 16 + dt) << 6) + lane * 2 + j;
                }
                outu[idx] = f2tf32(v);
            }
        }
    }
}

// ---------------------------------------------------------------------------
// tf32 mma.sync flash attention.
// BM=128 rows/CTA, BN=64 keys/tile, D=128. 8 warps, warp w owns rows
// [16w,16w+16) x all 64 cols -> softmax warp-local, P->A frags via shfl.
// K/V double-buffered via cp.async.
// ---------------------------------------------------------------------------
__global__ __launch_bounds__(256, 1) void flash_kernel(
    const float* __restrict__ Q, const float* __restrict__ K,
    const float* __restrict__ V, float* __restrict__ O)
{
    extern __shared__ float sm[];
    float* Qs = sm;                 // 16384 floats (64KB)
    float* Ks = sm + 16384;         // 2 x 8192 (2 x 32KB)
    float* Vs = sm + 32768;         // 2 x 8192

    const int b    = blockIdx.y;
    const int m0   = blockIdx.x * 128;
    const int tid  = threadIdx.x;
    const int w    = tid >> 5;
    const int lane = tid & 31;
    const int g    = lane >> 2;
    const int cq   = lane & 3;

    const float* Qg = Q + ((size_t)b * 256 + (m0 >> 4)) * 2048;  // 8 mt * 2048
    const float* Kg = K + (size_t)b * 524288;
    const float* Vg = V + (size_t)b * 524288;

    // Q tile: 16384 floats = 4096 float4
#pragma unroll
    for (int t = 0; t < 16; t++) {
        int f = tid + 256 * t;
        cp_async16(Qs + f * 4, Qg + f * 4);
    }
    CP_COMMIT();

    auto issueKV = [&](int i, int st) {
        const float* kg = Kg + (size_t)i * 8192;
        const float* vg = Vg + (size_t)i * 8192;
        float* ksd = Ks + st * 8192;
        float* vsd = Vs + st * 8192;
#pragma unroll
        for (int t = 0; t < 8; t++) {
            int f = tid + 256 * t;
            cp_async16(ksd + f * 4, kg + f * 4);
            cp_async16(vsd + f * 4, vg + f * 4);
        }
        CP_COMMIT();
    };
    issueKV(0, 0);
    issueKV(1, 1);

    float o[16][4];
#pragma unroll
    for (int dt = 0; dt < 16; dt++)
#pragma unroll
        for (int j = 0; j < 4; j++) o[dt][j] = 0.f;
    float m0r = -1e30f, m1r = -1e30f, l0 = 0.f, l1 = 0.f;

    for (int i = 0; i < 64; i++) {
        const int st = i & 1;
        cp_wait<1>();
        __syncthreads();

        const float* ksb = Ks + st * 8192;
        const float* vsb = Vs + st * 8192;

        // ---- S = Q @ K^T ----
        float sf[8][4];
#pragma unroll
        for (int nt = 0; nt < 8; nt++)
#pragma unroll
            for (int j = 0; j < 4; j++) sf[nt][j] = 0.f;

#pragma unroll
        for (int ks = 0; ks < 16; ks++) {
            uint4 a = *(const uint4*)(Qs + (w * 16 + ks) * 128 + lane * 4);
#pragma unroll
            for (int nt = 0; nt < 8; nt++) {
                uint2 bv = *(const uint2*)(ksb + (nt * 16 + ks) * 64 + lane * 2);
                mma_tf32(sf[nt], a.x, a.y, a.z, a.w, bv.x, bv.y);
            }
        }

        // ---- warp-local online softmax ----
        float mx0 = -1e30f, mx1 = -1e30f;
#pragma unroll
        for (int nt = 0; nt < 8; nt++) {
            mx0 = fmaxf(mx0, fmaxf(sf[nt][0], sf[nt][1]));
            mx1 = fmaxf(mx1, fmaxf(sf[nt][2], sf[nt][3]));
        }
        mx0 = fmaxf(mx0, __shfl_xor_sync(0xffffffffu, mx0, 1));
        mx0 = fmaxf(mx0, __shfl_xor_sync(0xffffffffu, mx0, 2));
        mx1 = fmaxf(mx1, __shfl_xor_sync(0xffffffffu, mx1, 1));
        mx1 = fmaxf(mx1, __shfl_xor_sync(0xffffffffu, mx1, 2));

        float nm0 = fmaxf(m0r, mx0), nm1 = fmaxf(m1r, mx1);
        float f0 = __expf(m0r - nm0), f1 = __expf(m1r - nm1);
        m0r = nm0; m1r = nm1;

        float s0 = 0.f, s1 = 0.f;
        uint32_t pb[8][4];
#pragma unroll
        for (int nt = 0; nt < 8; nt++) {
            float p0 = __expf(sf[nt][0] - nm0);
            float p1 = __expf(sf[nt][1] - nm0);
            float p2 = __expf(sf[nt][2] - nm1);
            float p3 = __expf(sf[nt][3] - nm1);
            s0 += p0 + p1; s1 += p2 + p3;
            pb[nt][0] = f2tf32(p0); pb[nt][1] = f2tf32(p1);
            pb[nt][2] = f2tf32(p2); pb[nt][3] = f2tf32(p3);
        }
        s0 += __shfl_xor_sync(0xffffffffu, s0, 1);
        s0 += __shfl_xor_sync(0xffffffffu, s0, 2);
        s1 += __shfl_xor_sync(0xffffffffu, s1, 1);
        s1 += __shfl_xor_sync(0xffffffffu, s1, 2);
        l0 = l0 * f0 + s0;
        l1 = l1 * f1 + s1;

#pragma unroll
        for (int dt = 0; dt < 16; dt++) {
            o[dt][0] *= f0; o[dt][1] *= f0;
            o[dt][2] *= f1; o[dt][3] *= f1;
        }

        // ---- PV: P C-frags -> A-frags via shfl, then mma over d-tiles ----
        const int src0 = (lane & 0x1c) | (cq >> 1);
        const int src1 = src0 + 2;
#pragma unroll
        for (int js = 0; js < 8; js++) {
            uint32_t x00 = __shfl_sync(0xffffffffu, pb[js][0], src0);
            uint32_t x01 = __shfl_sync(0xffffffffu, pb[js][1], src0);
            uint32_t x20 = __shfl_sync(0xffffffffu, pb[js][2], src0);
            uint32_t x21 = __shfl_sync(0xffffffffu, pb[js][3], src0);
            uint32_t y00 = __shfl_sync(0xffffffffu, pb[js][0], src1);
            uint32_t y01 = __shfl_sync(0xffffffffu, pb[js][1], src1);
            uint32_t y20 = __shfl_sync(0xffffffffu, pb[js][2], src1);
            uint32_t y21 = __shfl_sync(0xffffffffu, pb[js][3], src1);
            uint32_t a0 = (cq & 1) ? x01 : x00;
            uint32_t a1 = (cq & 1) ? x21 : x20;
            uint32_t a2 = (cq & 1) ? y01 : y00;
            uint32_t a3 = (cq & 1) ? y21 : y20;
#pragma unroll
            for (int dt = 0; dt < 16; dt++) {
                uint2 bv = *(const uint2*)(vsb + (js * 16 + dt) * 64 + lane * 2);
                mma_tf32(o[dt], a0, a1, a2, a3, bv.x, bv.y);
            }
        }

        __syncthreads();  // all warps done reading stage st before overwrite
        if (i + 2 < 64) issueKV(i + 2, st);
        else            CP_COMMIT();   // empty group keeps wait<1> accounting uniform
    }

    // ---- epilogue ----
    float inv0 = 1.0f / l0, inv1 = 1.0f / l1;
    float* Ob = O + ((size_t)b * NTOK + m0 + w * 16) * DH;
#pragma unroll
    for (int dt = 0; dt < 16; dt++) {
        float2 r0 = make_float2(o[dt][0] * inv0, o[dt][1] * inv0);
        float2 r1 = make_float2(o[dt][2] * inv1, o[dt][3] * inv1);
        *(float2*)(Ob + g * DH + dt * 8 + 2 * cq)       = r0;
        *(float2*)(Ob + (g + 8) * DH + dt * 8 + 2 * cq) = r1;
    }
}

static const int FLASH_SMEM = 49152 * 4;  // 192 KB

extern "C" void kernel_launch(void* const* d_in, const int* in_sizes, int n_in,
                              void* d_out, int out_size)
{
    const float* x_upper = (const float*)d_in[0];
    const float* x_lower = (const float*)d_in[1];
    const float* wq = (const float*)d_in[2];
    const float* bq = (const float*)d_in[3];
    const float* wk = (const float*)d_in[4];
    const float* bk = (const float*)d_in[5];
    const float* wv = (const float*)d_in[6];
    const float* bv = (const float*)d_in[7];
    const float* wo = (const float*)d_in[8];
    const float* bo = (const float*)d_in[9];
    float* out = (float*)d_out;

    float *Qp, *Kp, *Vp, *Op;
    cudaGetSymbolAddress((void**)&Qp, g_Q);
    cudaGetSymbolAddress((void**)&Kp, g_K);
    cudaGetSymbolAddress((void**)&Vp, g_V);
    cudaGetSymbolAddress((void**)&Op, g_O);

    cudaFuncSetAttribute(flash_kernel,
                         cudaFuncAttributeMaxDynamicSharedMemorySize, FLASH_SMEM);

    dim3 pb(256);
    dim3 pg(HW / 256, DH / 32, NB);  // (16, 4, 4)

    proj_kernel<64,  1, false><<<pg, pb>>>(x_upper, wq, bq, nullptr, Qp);
    proj_kernel<128, 2, false><<<pg, pb>>>(x_lower, wk, bk, nullptr, Kp);
    proj_kernel<128, 3, false><<<pg, pb>>>(x_lower, wv, bv, nullptr, Vp);

    flash_kernel<<<dim3(NTOK / 128, NB), 256, FLASH_SMEM>>>(Qp, Kp, Vp, Op);

    proj_kernel<128, 0, true><<<pg, pb>>>(Op, wo, bo, x_lower, out);
}

// round 3
// speedup vs baseline: 5.6513x; 1.5705x over previous
#include <cuda_runtime.h>
#include <math.h>
#include <stdint.h>

#define NB   4
#define HW   4096
#define DH   128
#define NTOK 4096
#define QKV_U32 (NTOK * DH / 2)   // 262144 uint32 (bf16x2) per batch

// Scratch (device globals; allocation-free).
// Q: A-frag m16n8k16  [b][mt(256)][ks(8)][lane(32)][4]  (bf16x2 per u32)
// K: B-frag           [b][nt(512)][ks(8)][lane(32)][2]
// V: B-frag           [b][js(256)][dt(16)][lane(32)][2]
// O: plain fp32       [b][n][d]  (== NCHW flat)
__device__ uint32_t g_Q[NB * QKV_U32];
__device__ uint32_t g_K[NB * QKV_U32];
__device__ uint32_t g_V[NB * QKV_U32];
__device__ float    g_O[NB * NTOK * DH];

__device__ __forceinline__ uint32_t pack_bf16(float lo, float hi) {
    uint32_t r;
    asm("cvt.rn.bf16x2.f32 %0, %1, %2;" : "=r"(r) : "f"(hi), "f"(lo));
    return r;
}
__device__ __forceinline__ uint16_t bf16_bits(float x) {
    uint16_t r;
    asm("{.reg .b16 lo, hi; mov.b32 {lo, hi}, %1; cvt.rn.bf16.f32 hi, %1; mov.b16 %0, hi;}"
        : "=h"(r) : "f"(x));
    return r;
}
__device__ __forceinline__ float ex2f(float x) {
    float y; asm("ex2.approx.f32 %0, %1;" : "=f"(y) : "f"(x)); return y;
}
__device__ __forceinline__ void mma_bf16(float* d,
    uint32_t a0, uint32_t a1, uint32_t a2, uint32_t a3,
    uint32_t b0, uint32_t b1)
{
    asm volatile(
        "mma.sync.aligned.m16n8k16.row.col.f32.bf16.bf16.f32 "
        "{%0,%1,%2,%3},{%4,%5,%6,%7},{%8,%9},{%0,%1,%2,%3};"
        : "+f"(d[0]), "+f"(d[1]), "+f"(d[2]), "+f"(d[3])
        : "r"(a0), "r"(a1), "r"(a2), "r"(a3), "r"(b0), "r"(b1));
}
__device__ __forceinline__ void cp_async16(void* smem_dst, const void* gmem_src) {
    uint32_t s = (uint32_t)__cvta_generic_to_shared(smem_dst);
    asm volatile("cp.async.cg.shared.global [%0], [%1], 16;\n" :: "r"(s), "l"(gmem_src));
}
#define CP_COMMIT() asm volatile("cp.async.commit_group;\n" ::: "memory")
template<int N> __device__ __forceinline__ void cp_wait() {
    asm volatile("cp.async.wait_group %0;\n" :: "n"(N) : "memory");
}

// log2(e)/sqrt(128): Q pre-scale so softmax runs in exp2 domain.
#define QSCALE (0.08838834764831845f * 1.4426950408889634f)

// ---------------------------------------------------------------------------
// 1x1 conv (GEMM). MODE: 0 = fp32 NCHW out (+residual),
//   1 = Q A-frag bf16 (pre-scaled), 2 = K B-frag bf16, 3 = V B-frag bf16.
// ---------------------------------------------------------------------------
template<int CIN, int MODE, bool RES>
__global__ __launch_bounds__(256) void proj_kernel(
    const float* __restrict__ x, const float* __restrict__ w,
    const float* __restrict__ bias, const float* __restrict__ res,
    float* __restrict__ out)
{
    __shared__ float xs[16][256];
    __shared__ float ws[32][16];

    const int b   = blockIdx.z;
    const int c0  = blockIdx.y * 32;
    const int s0  = blockIdx.x * 256;
    const int tid = threadIdx.x;
    const int tx  = tid & 63;
    const int ty  = tid >> 6;

    float acc[8][4];
#pragma unroll
    for (int i = 0; i < 8; i++)
#pragma unroll
        for (int j = 0; j < 4; j++) acc[i][j] = 0.f;

    for (int k0 = 0; k0 < CIN; k0 += 16) {
        __syncthreads();
#pragma unroll
        for (int t = 0; t < 4; t++) {
            int f  = tid + 256 * t;
            int r  = f >> 6;
            int c4 = (f & 63) << 2;
            float4 v = *(const float4*)(x + ((size_t)b * CIN + k0 + r) * HW + s0 + c4);
            *(float4*)&xs[r][c4] = v;
        }
#pragma unroll
        for (int t = 0; t < 2; t++) {
            int f  = tid + 256 * t;
            int cr = f >> 4, ck = f & 15;
            ws[cr][ck] = w[(size_t)(c0 + cr) * CIN + k0 + ck];
        }
        __syncthreads();
#pragma unroll
        for (int k = 0; k < 16; k++) {
            float4 xv = *(float4*)&xs[k][tx << 2];
#pragma unroll
            for (int cc = 0; cc < 8; cc++) {
                float wv = ws[ty * 8 + cc][k];
                acc[cc][0] = fmaf(wv, xv.x, acc[cc][0]);
                acc[cc][1] = fmaf(wv, xv.y, acc[cc][1]);
                acc[cc][2] = fmaf(wv, xv.z, acc[cc][2]);
                acc[cc][3] = fmaf(wv, xv.w, acc[cc][3]);
            }
        }
    }

    uint32_t* outu = (uint32_t*)out;
    uint16_t* outh = (uint16_t*)out;

#pragma unroll
    for (int cc = 0; cc < 8; cc++) {
        const int c  = c0 + ty * 8 + cc;
        const float bv = bias[c];
        const int s  = s0 + (tx << 2);
        if (MODE == 0) {
            float4 o;
            o.x = acc[cc][0] + bv; o.y = acc[cc][1] + bv;
            o.z = acc[cc][2] + bv; o.w = acc[cc][3] + bv;
            if (RES) {
                float4 rv = *(const float4*)(res + ((size_t)b * DH + c) * HW + s);
                o.x += rv.x; o.y += rv.y; o.z += rv.z; o.w += rv.w;
            }
            *(float4*)(out + ((size_t)b * DH + c) * HW + s) = o;
        } else {
            // token n, channel-dim d: flat = c*4096 + s; n = flat>>7, d = flat&127.
            const int d0 = s & 127;       // aligned to 4
            const int n  = c * 32 + (s >> 7);
            float v0 = acc[cc][0] + bv, v1 = acc[cc][1] + bv;
            float v2 = acc[cc][2] + bv, v3 = acc[cc][3] + bv;
            if (MODE == 1) {              // Q: A-frag, pre-scaled
                v0 *= QSCALE; v1 *= QSCALE; v2 *= QSCALE; v3 *= QSCALE;
                int mt = n >> 4, r = n & 15;
                int grow = r & 7, hi = r >> 3;
                int ks = d0 >> 4, kk = d0 & 15;
                int ch = kk >> 3;
                int t0 = (kk & 7) >> 1;   // 0 or 2
                int lane = grow * 4 + t0;
                int j = hi + 2 * ch;
                size_t base = (((size_t)b * 256 + mt) * 8 + ks) * 128 + lane * 4 + j;
                outu[base]     = pack_bf16(v0, v1);
                outu[base + 4] = pack_bf16(v2, v3);
            } else if (MODE == 2) {       // K: B-frag, k=d, n=token
                int nt = n >> 3, g = n & 7;
                int ks = d0 >> 4, kk = d0 & 15;
                int j = kk >> 3;
                int t0 = (kk & 7) >> 1;
                int lane = g * 4 + t0;
                size_t base = (((size_t)b * 512 + nt) * 8 + ks) * 64 + lane * 2 + j;
                outu[base]     = pack_bf16(v0, v1);
                outu[base + 2] = pack_bf16(v2, v3);
            } else {                      // V: B-frag, k=token, n=d
                int js = n >> 4, r = n & 15;
                int j = r >> 3, t = (r & 7) >> 1, par = r & 1;
                float vv[4] = {v0, v1, v2, v3};
#pragma unroll
                for (int u = 0; u < 4; u++) {
                    int d = d0 + u;
                    int dt = d >> 3, g = d & 7;
                    int lane = g * 4 + t;
                    size_t u32i = (((size_t)b * 256 + js) * 16 + dt) * 64 + lane * 2 + j;
                    outh[u32i * 2 + par] = bf16_bits(vv[u]);
                }
            }
        }
    }
}

// ---------------------------------------------------------------------------
// bf16 m16n8k16 flash attention. BM=128/CTA, BN=64 key tile, D=128.
// 8 warps; warp w owns rows [16w,16w+16) x all 64 cols (softmax warp-local).
// P C-frags repack directly into A-frags (no shuffles). 4-stage cp.async.
// ---------------------------------------------------------------------------
__global__ __launch_bounds__(256, 1) void flash_kernel(
    const uint32_t* __restrict__ Q, const uint32_t* __restrict__ K,
    const uint32_t* __restrict__ V, float* __restrict__ O)
{
    extern __shared__ uint32_t sm[];
    uint32_t* Qs = sm;            // 8192 u32 (32KB)
    uint32_t* Ks = sm + 8192;     // 4 stages x 4096 u32 (4 x 16KB)
    uint32_t* Vs = sm + 8192 + 16384;  // 4 stages x 4096 u32

    const int b    = blockIdx.y;
    const int m0   = blockIdx.x * 128;
    const int tid  = threadIdx.x;
    const int w    = tid >> 5;
    const int lane = tid & 31;
    const int g    = lane >> 2;
    const int t    = lane & 3;

    const uint32_t* Qg = Q + (size_t)b * QKV_U32 + (size_t)blockIdx.x * 8192;
    const uint32_t* Kg = K + (size_t)b * QKV_U32;
    const uint32_t* Vg = V + (size_t)b * QKV_U32;

    // Q tile: 8192 u32 = 2048 float4
#pragma unroll
    for (int tt = 0; tt < 8; tt++) {
        int f = tid + 256 * tt;
        cp_async16(Qs + f * 4, Qg + f * 4);
    }
    CP_COMMIT();

    auto issueKV = [&](int i, int st) {
#pragma unroll
        for (int tt = 0; tt < 4; tt++) {
            int f = tid + 256 * tt;
            cp_async16(Ks + st * 4096 + f * 4, Kg + (size_t)i * 4096 + f * 4);
            cp_async16(Vs + st * 4096 + f * 4, Vg + (size_t)i * 4096 + f * 4);
        }
        CP_COMMIT();
    };
    issueKV(0, 0);
    issueKV(1, 1);
    issueKV(2, 2);

    float o[16][4];
#pragma unroll
    for (int dt = 0; dt < 16; dt++)
#pragma unroll
        for (int j = 0; j < 4; j++) o[dt][j] = 0.f;
    float m0r = -1e30f, m1r = -1e30f, l0 = 0.f, l1 = 0.f;

    const uint32_t* qw = Qs + w * 1024;   // warp's mt block: 8 ks x 128

    for (int i = 0; i < 64; i++) {
        const int st = i & 3;
        cp_wait<2>();
        __syncthreads();
        // prefetch tile i+3 into stage (i+3)&3 (read last at iter i-1; safe after sync)
        if (i + 3 < 64) issueKV(i + 3, (i + 3) & 3);
        else            CP_COMMIT();

        const uint32_t* ksb = Ks + st * 4096;
        const uint32_t* vsb = Vs + st * 4096;

        // ---- S = Q @ K^T (exp2 domain; Q pre-scaled) ----
        float sf[8][4];
#pragma unroll
        for (int nt = 0; nt < 8; nt++)
#pragma unroll
            for (int j = 0; j < 4; j++) sf[nt][j] = 0.f;

#pragma unroll
        for (int ks = 0; ks < 8; ks++) {
            uint4 a = *(const uint4*)(qw + ks * 128 + lane * 4);
#pragma unroll
            for (int nt = 0; nt < 8; nt++) {
                uint2 bv = *(const uint2*)(ksb + (nt * 8 + ks) * 64 + lane * 2);
                mma_bf16(sf[nt], a.x, a.y, a.z, a.w, bv.x, bv.y);
            }
        }

        // ---- warp-local online softmax (base-2) ----
        float mx0 = -1e30f, mx1 = -1e30f;
#pragma unroll
        for (int nt = 0; nt < 8; nt++) {
            mx0 = fmaxf(mx0, fmaxf(sf[nt][0], sf[nt][1]));
            mx1 = fmaxf(mx1, fmaxf(sf[nt][2], sf[nt][3]));
        }
        mx0 = fmaxf(mx0, __shfl_xor_sync(0xffffffffu, mx0, 1));
        mx0 = fmaxf(mx0, __shfl_xor_sync(0xffffffffu, mx0, 2));
        mx1 = fmaxf(mx1, __shfl_xor_sync(0xffffffffu, mx1, 1));
        mx1 = fmaxf(mx1, __shfl_xor_sync(0xffffffffu, mx1, 2));

        float nm0 = fmaxf(m0r, mx0), nm1 = fmaxf(m1r, mx1);
        float f0 = ex2f(m0r - nm0), f1 = ex2f(m1r - nm1);
        m0r = nm0; m1r = nm1;

        float s0 = 0.f, s1 = 0.f;
#pragma unroll
        for (int nt = 0; nt < 8; nt++) {
            sf[nt][0] = ex2f(sf[nt][0] - nm0);
            sf[nt][1] = ex2f(sf[nt][1] - nm0);
            sf[nt][2] = ex2f(sf[nt][2] - nm1);
            sf[nt][3] = ex2f(sf[nt][3] - nm1);
            s0 += sf[nt][0] + sf[nt][1];
            s1 += sf[nt][2] + sf[nt][3];
        }
        s0 += __shfl_xor_sync(0xffffffffu, s0, 1);
        s0 += __shfl_xor_sync(0xffffffffu, s0, 2);
        s1 += __shfl_xor_sync(0xffffffffu, s1, 1);
        s1 += __shfl_xor_sync(0xffffffffu, s1, 2);
        l0 = l0 * f0 + s0;
        l1 = l1 * f1 + s1;

#pragma unroll
        for (int dt = 0; dt < 16; dt++) {
            o[dt][0] *= f0; o[dt][1] *= f0;
            o[dt][2] *= f1; o[dt][3] *= f1;
        }

        // ---- PV: P C-frags pack straight into A-frags (no shuffle) ----
#pragma unroll
        for (int u = 0; u < 4; u++) {
            uint32_t a0 = pack_bf16(sf[2*u][0],   sf[2*u][1]);
            uint32_t a1 = pack_bf16(sf[2*u][2],   sf[2*u][3]);
            uint32_t a2 = pack_bf16(sf[2*u+1][0], sf[2*u+1][1]);
            uint32_t a3 = pack_bf16(sf[2*u+1][2], sf[2*u+1][3]);
#pragma unroll
            for (int dt = 0; dt < 16; dt++) {
                uint2 bv = *(const uint2*)(vsb + (u * 16 + dt) * 64 + lane * 2);
                mma_bf16(o[dt], a0, a1, a2, a3, bv.x, bv.y);
            }
        }
    }

    // ---- epilogue: O = acc / l ----
    float inv0 = 1.0f / l0, inv1 = 1.0f / l1;
    float* Ob = O + ((size_t)b * NTOK + m0 + w * 16) * DH;
#pragma unroll
    for (int dt = 0; dt < 16; dt++) {
        float2 r0 = make_float2(o[dt][0] * inv0, o[dt][1] * inv0);
        float2 r1 = make_float2(o[dt][2] * inv1, o[dt][3] * inv1);
        *(float2*)(Ob + g * DH + dt * 8 + 2 * t)       = r0;
        *(float2*)(Ob + (g + 8) * DH + dt * 8 + 2 * t) = r1;
    }
}

static const int FLASH_SMEM = (8192 + 16384 + 16384) * 4;  // 160 KB

extern "C" void kernel_launch(void* const* d_in, const int* in_sizes, int n_in,
                              void* d_out, int out_size)
{
    const float* x_upper = (const float*)d_in[0];
    const float* x_lower = (const float*)d_in[1];
    const float* wq = (const float*)d_in[2];
    const float* bq = (const float*)d_in[3];
    const float* wk = (const float*)d_in[4];
    const float* bk = (const float*)d_in[5];
    const float* wv = (const float*)d_in[6];
    const float* bv = (const float*)d_in[7];
    const float* wo = (const float*)d_in[8];
    const float* bo = (const float*)d_in[9];
    float* out = (float*)d_out;

    uint32_t *Qp, *Kp, *Vp; float* Op;
    cudaGetSymbolAddress((void**)&Qp, g_Q);
    cudaGetSymbolAddress((void**)&Kp, g_K);
    cudaGetSymbolAddress((void**)&Vp, g_V);
    cudaGetSymbolAddress((void**)&Op, g_O);

    cudaFuncSetAttribute(flash_kernel,
                         cudaFuncAttributeMaxDynamicSharedMemorySize, FLASH_SMEM);

    dim3 pb(256);
    dim3 pg(HW / 256, DH / 32, NB);  // (16, 4, 4)

    proj_kernel<64,  1, false><<<pg, pb>>>(x_upper, wq, bq, nullptr, (float*)Qp);
    proj_kernel<128, 2, false><<<pg, pb>>>(x_lower, wk, bk, nullptr, (float*)Kp);
    proj_kernel<128, 3, false><<<pg, pb>>>(x_lower, wv, bv, nullptr, (float*)Vp);

    flash_kernel<<<dim3(NTOK / 128, NB), 256, FLASH_SMEM>>>(Qp, Kp, Vp, Op);

    proj_kernel<128, 0, true><<<pg, pb>>>(Op, wo, bo, x_lower, out);
}